// round 9
// baseline (speedup 1.0000x reference)
#include <cuda_runtime.h>
#include <cuda_bf16.h>
#include <cstdint>

#define D        64
#define K        1024
#define NVEC     65536
#define QELEMS   (NVEC * D)
#define MTILE    128
#define NCHUNK   64
#define QCHUNKS  4                 // chunks per quarter (256 codewords)
#define NQUART   4
#define NTILES   (NVEC / MTILE)    // 512
#define NUNITS   (NTILES * NQUART) // 2048
#define CTAS     296               // 2 per SM, persistent
#define EPS      0.003f

// smem offsets
#define OFF_A    0            // 128 rows x 256B (swizzled) = 32768
#define OFF_B    32768        // 2 stages x 24576 (B1 16K + B2 8K)
#define OFF_SN   81920        // 1024 floats = 4096
#define OFF_RED  86016        // 8 floats (warp loss partials)
#define OFF_LAST 86048        // 1 int
#define SMEM_SZ  86144

__device__ __nv_bfloat16 g_B1[K * 128];      // per codeword: [h | h]
__device__ __nv_bfloat16 g_B2[K * 64];       // per codeword: [m]
__device__ float g_enorm2[K];
__device__ float g_pb1[NQUART * NVEC];
__device__ float g_pb2[NQUART * NVEC];
__device__ int   g_pidx[NQUART * NVEC];
__device__ int   g_tile_ctr[NTILES];
__device__ int   g_flag_list[NVEC];
__device__ int   g_flag_count;

// ---------- helpers ----------
__device__ __forceinline__ uint32_t smem_u32(const void* p) {
    uint32_t a;
    asm("{ .reg .u64 t; cvta.to.shared.u64 t, %1; cvt.u32.u64 %0, t; }" : "=r"(a) : "l"(p));
    return a;
}
__device__ __forceinline__ void cp16(uint32_t dst, const void* src) {
    asm volatile("cp.async.cg.shared.global [%0], [%1], 16;" :: "r"(dst), "l"(src));
}
__device__ __forceinline__ void cp_commit() { asm volatile("cp.async.commit_group;" ::: "memory"); }
template<int N> __device__ __forceinline__ void cp_wait() {
    asm volatile("cp.async.wait_group %0;" :: "n"(N) : "memory");
}
__device__ __forceinline__ void ldsm4(uint32_t* r, uint32_t addr) {
    asm volatile("ldmatrix.sync.aligned.m8n8.x4.shared.b16 {%0,%1,%2,%3}, [%4];"
                 : "=r"(r[0]), "=r"(r[1]), "=r"(r[2]), "=r"(r[3]) : "r"(addr));
}
__device__ __forceinline__ void mma16816(float* c, const uint32_t* a, uint32_t b0, uint32_t b1) {
    asm volatile(
        "mma.sync.aligned.m16n8k16.row.col.f32.bf16.bf16.f32 "
        "{%0,%1,%2,%3}, {%4,%5,%6,%7}, {%8,%9}, {%0,%1,%2,%3};"
        : "+f"(c[0]), "+f"(c[1]), "+f"(c[2]), "+f"(c[3])
        : "r"(a[0]), "r"(a[1]), "r"(a[2]), "r"(a[3]), "r"(b0), "r"(b1));
}
__device__ __forceinline__ void sts16(uint32_t addr, uint4 v) {
    asm volatile("st.shared.v4.b32 [%0], {%1, %2, %3, %4};"
                 :: "r"(addr), "r"(v.x), "r"(v.y), "r"(v.z), "r"(v.w));
}

// ---------- codebook conversion ----------
__global__ void __launch_bounds__(256) vq_convE(const float* __restrict__ emb) {
    int t = blockIdx.x * 256 + threadIdx.x;     // 0 .. 8K-1
    if (t == 0) g_flag_count = 0;
    int k = t >> 3, j = t & 7;
    const float4* er = reinterpret_cast<const float4*>(emb + (size_t)k * D + j * 8);
    float4 a = er[0], b = er[1];
    float f[8] = {a.x, a.y, a.z, a.w, b.x, b.y, b.z, b.w};
    __nv_bfloat16 h[8], m[8];
    float s = 0.f;
#pragma unroll
    for (int e = 0; e < 8; e++) {
        s += f[e] * f[e];
        h[e] = __float2bfloat16_rn(f[e]);
        m[e] = __float2bfloat16_rn(f[e] - __bfloat162float(h[e]));
    }
    uint4 hv = *reinterpret_cast<uint4*>(h);
    uint4 mv = *reinterpret_cast<uint4*>(m);
    uint4* r1 = reinterpret_cast<uint4*>(g_B1 + (size_t)k * 128 + j * 8);
    r1[0] = hv; r1[8] = hv;                     // [h | h]
    *reinterpret_cast<uint4*>(g_B2 + (size_t)k * 64 + j * 8) = mv;
#pragma unroll
    for (int off = 4; off > 0; off >>= 1) s += __shfl_xor_sync(0xffffffffu, s, off);
    if (j == 0) g_enorm2[k] = s;
}

// load one B chunk: B1 (64 rows x 256B) + B2 (64 rows x 128B)
__device__ __forceinline__ void load_B(uint32_t sb, int chunk, int stage, int tid) {
    uint32_t base = sb + OFF_B + stage * 24576;
    const char* s1 = reinterpret_cast<const char*>(g_B1 + (size_t)chunk * NCHUNK * 128);
    const char* s2 = reinterpret_cast<const char*>(g_B2 + (size_t)chunk * NCHUNK * 64);
#pragma unroll
    for (int it = 0; it < 4; it++) {
        int i = tid + it * 256;
        int row = i >> 4, seg = i & 15;
        cp16(base + row * 256 + ((seg ^ (row & 7)) << 4), s1 + row * 256 + seg * 16);
    }
#pragma unroll
    for (int it = 0; it < 2; it++) {
        int i = tid + it * 256;
        int row = i >> 3, seg = i & 7;
        cp16(base + 16384 + row * 128 + ((seg ^ (row & 7)) << 4), s2 + row * 128 + seg * 16);
    }
}

#define UPD(dv, nn, B1v, I1v, B2v) \
    if ((dv) < (B1v)) { (B2v) = (B1v); (B1v) = (dv); (I1v) = (nn); } \
    else if ((dv) < (B2v)) { (B2v) = (dv); }

// ---------- persistent mega kernel: units = (M-tile, codebook quarter) ----------
__global__ void __launch_bounds__(256, 2) vq_gemm(const float* __restrict__ x,
                                                  const float* __restrict__ emb,
                                                  float* __restrict__ out, int out_size) {
    extern __shared__ char sm[];
    uint32_t sb = smem_u32(sm);
    const int tid = threadIdx.x, wid = tid >> 5, l = tid & 31;
    float* sred  = reinterpret_cast<float*>(sm + OFF_RED);
    int*   slast = reinterpret_cast<int*>(sm + OFF_LAST);

    for (int u = blockIdx.x; u < NUNITS; u += CTAS) {
        const int mtile = u >> 2, q = u & 3;
        __syncthreads();                        // previous unit fully done with smem

        // async: e-norms + B chunks q*4, q*4+1
        cp16(sb + OFF_SN + tid * 16, reinterpret_cast<const char*>(g_enorm2) + tid * 16);
        load_B(sb, q * QCHUNKS + 0, 0, tid);
        cp_commit();                            // G0
        load_B(sb, q * QCHUNKS + 1, 1, tid);
        cp_commit();                            // G1

        // A tile: load fp32 x, split h/m in regs, STS swizzled
        {
            const int row = tid >> 1, hf = tid & 1;
            const float4* xr = reinterpret_cast<const float4*>(
                x + (size_t)(mtile * MTILE + row) * D + hf * 32);
            uint32_t abase = sb + OFF_A + row * 256;
#pragma unroll
            for (int i = 0; i < 4; i++) {
                float4 a = xr[2 * i], b = xr[2 * i + 1];
                float f[8] = {a.x, a.y, a.z, a.w, b.x, b.y, b.z, b.w};
                __nv_bfloat16 h[8], m[8];
#pragma unroll
                for (int e = 0; e < 8; e++) {
                    h[e] = __float2bfloat16_rn(f[e]);
                    m[e] = __float2bfloat16_rn(f[e] - __bfloat162float(h[e]));
                }
                int segh = hf * 4 + i;
                int segm = 8 + hf * 4 + i;
                sts16(abase + ((segh ^ (row & 7)) << 4), *reinterpret_cast<uint4*>(h));
                sts16(abase + ((segm ^ (row & 7)) << 4), *reinterpret_cast<uint4*>(m));
            }
        }

        cp_wait<1>();                           // sn + B(q*4) resident
        __syncthreads();

        uint32_t aF[8][4];
        {
            int row = (wid << 4) + (l & 15);
            uint32_t rb = sb + OFF_A + row * 256;
#pragma unroll
            for (int j = 0; j < 8; j++) {
                int seg = j * 2 + (l >> 4);
                ldsm4(aF[j], rb + ((seg ^ (row & 7)) << 4));
            }
        }
        const float* snp = reinterpret_cast<const float*>(sm + OFF_SN);

        float b1a = 3.4e38f, b2a = 3.4e38f, b1b = 3.4e38f, b2b = 3.4e38f;
        int i1a = 0, i1b = 0;

        for (int c = 0; c < QCHUNKS; c++) {
            if (c > 0) { cp_wait<1>(); __syncthreads(); }
            uint32_t stage = sb + OFF_B + (c & 1) * 24576;

            float C[8][4];
#pragma unroll
            for (int t = 0; t < 8; t++) { C[t][0] = C[t][1] = C[t][2] = C[t][3] = 0.f; }

            // [h|m] x [h|h] (8 k-steps)
#pragma unroll
            for (int j = 0; j < 8; j++) {
#pragma unroll
                for (int g = 0; g < 4; g++) {
                    int row = (g << 4) + (l & 15);
                    int seg = j * 2 + (l >> 4);
                    uint32_t r[4];
                    ldsm4(r, stage + row * 256 + ((seg ^ (row & 7)) << 4));
                    mma16816(C[2 * g],     aF[j], r[0], r[2]);
                    mma16816(C[2 * g + 1], aF[j], r[1], r[3]);
                }
            }
            // h x [m] (4 k-steps)
#pragma unroll
            for (int j = 0; j < 4; j++) {
#pragma unroll
                for (int g = 0; g < 4; g++) {
                    int row = (g << 4) + (l & 15);
                    int seg = j * 2 + (l >> 4);
                    uint32_t r[4];
                    ldsm4(r, stage + 16384 + row * 128 + ((seg ^ (row & 7)) << 4));
                    mma16816(C[2 * g],     aF[j], r[0], r[2]);
                    mma16816(C[2 * g + 1], aF[j], r[1], r[3]);
                }
            }

#pragma unroll
            for (int t = 0; t < 8; t++) {
                int n0 = (q * QCHUNKS + c) * NCHUNK + t * 8 + 2 * (l & 3);
                float s0 = snp[n0 & 1023], s1 = snp[(n0 + 1) & 1023];
                float d;
                d = fmaf(-2.f, C[t][0], s0); UPD(d, n0,     b1a, i1a, b2a);
                d = fmaf(-2.f, C[t][1], s1); UPD(d, n0 + 1, b1a, i1a, b2a);
                d = fmaf(-2.f, C[t][2], s0); UPD(d, n0,     b1b, i1b, b2b);
                d = fmaf(-2.f, C[t][3], s1); UPD(d, n0 + 1, b1b, i1b, b2b);
            }

            __syncthreads();
            if (c + 2 < QCHUNKS) load_B(sb, q * QCHUNKS + c + 2, c & 1, tid);
            cp_commit();
        }

        // cross-lane merge within 4-lane groups
#pragma unroll
        for (int off = 1; off <= 2; off <<= 1) {
            float p1 = __shfl_xor_sync(0xffffffffu, b1a, off);
            int   pi = __shfl_xor_sync(0xffffffffu, i1a, off);
            float p2 = __shfl_xor_sync(0xffffffffu, b2a, off);
            if (p1 < b1a || (p1 == b1a && pi < i1a)) { b2a = fminf(b1a, p2); b1a = p1; i1a = pi; }
            else                                      { b2a = fminf(b2a, p1); }
            p1 = __shfl_xor_sync(0xffffffffu, b1b, off);
            pi = __shfl_xor_sync(0xffffffffu, i1b, off);
            p2 = __shfl_xor_sync(0xffffffffu, b2b, off);
            if (p1 < b1b || (p1 == b1b && pi < i1b)) { b2b = fminf(b1b, p2); b1b = p1; i1b = pi; }
            else                                      { b2b = fminf(b2b, p1); }
        }

        // write quarter partials
        if ((l & 3) == 0) {
            int r0 = wid * 16 + (l >> 2);
            int v = mtile * MTILE + r0;
            g_pb1[q * NVEC + v] = b1a;  g_pb2[q * NVEC + v] = b2a;  g_pidx[q * NVEC + v] = i1a;
            g_pb1[q * NVEC + v + 8] = b1b; g_pb2[q * NVEC + v + 8] = b2b; g_pidx[q * NVEC + v + 8] = i1b;
        }
        __syncthreads();
        if (tid == 0) {
            __threadfence();
            int old = atomicAdd(&g_tile_ctr[mtile], 1);
            *slast = (old == 3);
        }
        __syncthreads();

        if (*slast) {
            __threadfence();                    // acquire: other quarters' partials visible
            const int r = tid >> 1, hf = tid & 1;
            const int v = mtile * MTILE + r;
            float b1 = __ldcg(&g_pb1[v]), b2 = __ldcg(&g_pb2[v]);
            int   bi = __ldcg(&g_pidx[v]);
#pragma unroll
            for (int qq = 1; qq < 4; qq++) {    // ascending quarter order -> first-min tiebreak
                float a1 = __ldcg(&g_pb1[qq * NVEC + v]);
                float a2 = __ldcg(&g_pb2[qq * NVEC + v]);
                int   ai = __ldcg(&g_pidx[qq * NVEC + v]);
                if (a1 < b1) { b2 = fminf(b1, a2); b1 = a1; bi = ai; }
                else         { b2 = fminf(b2, a1); }
            }
            bool flg = (b2 - b1 <= EPS);
            float lsum = 0.f;
            if (!flg) {
                const float4* er = reinterpret_cast<const float4*>(emb + (size_t)bi * D + hf * 32);
                const float4* xr = reinterpret_cast<const float4*>(x + (size_t)v * D + hf * 32);
                float4* o = reinterpret_cast<float4*>(out + (size_t)v * D + hf * 32);
#pragma unroll
                for (int i = 0; i < 8; i++) {
                    float4 e = er[i]; float4 xx = xr[i];
                    float dx = e.x - xx.x, dy = e.y - xx.y, dz = e.z - xx.z, dw = e.w - xx.w;
                    lsum += dx * dx + dy * dy + dz * dz + dw * dw;
                    float4 qv;  // quantized = x + (e - x)
                    qv.x = xx.x + dx; qv.y = xx.y + dy; qv.z = xx.z + dz; qv.w = xx.w + dw;
                    o[i] = qv;
                }
                if (hf == 0 && QELEMS + 1 + v < out_size) out[QELEMS + 1 + v] = (float)bi;
            } else if (hf == 0) {
                int s = atomicAdd(&g_flag_count, 1); g_flag_list[s] = v;
            }
            // block loss reduction -> 1 atomic per tile
#pragma unroll
            for (int off = 16; off > 0; off >>= 1)
                lsum += __shfl_down_sync(0xffffffffu, lsum, off);
            if (l == 0) sred[wid] = lsum;
            __syncthreads();
            if (wid == 0) {
                float s = (l < 8) ? sred[l] : 0.f;
#pragma unroll
                for (int off = 4; off > 0; off >>= 1)
                    s += __shfl_down_sync(0xffffffffu, s, off);
                if (l == 0 && out_size > QELEMS)
                    atomicAdd(out + QELEMS, s * (0.25f / (float)QELEMS));
            }
        }
    }
}

// ---------- exact rescan + full finalize for flagged vectors ----------
__global__ void __launch_bounds__(256) vq_rescan(const float* __restrict__ x,
                                                 const float* __restrict__ emb,
                                                 float* __restrict__ out, int out_size) {
    __shared__ float sx[64];
    __shared__ float sbest[256];
    __shared__ int   sidx[256];
    int n = g_flag_count;
    if (n > NVEC) n = NVEC;
    for (int vi = blockIdx.x; vi < n; vi += gridDim.x) {
        int v = g_flag_list[vi];
        __syncthreads();
        if (threadIdx.x < 16)
            reinterpret_cast<float4*>(sx)[threadIdx.x] =
                reinterpret_cast<const float4*>(x + (size_t)v * D)[threadIdx.x];
        __syncthreads();
        float best = 3.4e38f; int bi = K;
#pragma unroll
        for (int kk = 0; kk < 4; kk++) {
            int k = kk * 256 + threadIdx.x;
            const float4* er = reinterpret_cast<const float4*>(emb + (size_t)k * D);
            float dot = 0.f;
#pragma unroll
            for (int i = 0; i < 16; i++) {
                float4 e = er[i];
                dot += sx[4*i] * e.x + sx[4*i+1] * e.y + sx[4*i+2] * e.z + sx[4*i+3] * e.w;
            }
            float d = fmaf(-2.f, dot, g_enorm2[k]);
            if (d < best) { best = d; bi = k; }
        }
        sbest[threadIdx.x] = best; sidx[threadIdx.x] = bi;
        __syncthreads();
        for (int s = 128; s > 0; s >>= 1) {
            if (threadIdx.x < s) {
                float ob = sbest[threadIdx.x + s]; int oi = sidx[threadIdx.x + s];
                if (ob < sbest[threadIdx.x] ||
                    (ob == sbest[threadIdx.x] && oi < sidx[threadIdx.x])) {
                    sbest[threadIdx.x] = ob; sidx[threadIdx.x] = oi;
                }
            }
            __syncthreads();
        }
        int bfin = sidx[0];
        float lsum = 0.f;
        if (threadIdx.x < 16) {
            float4 e  = reinterpret_cast<const float4*>(emb + (size_t)bfin * D)[threadIdx.x];
            float4 xx = reinterpret_cast<const float4*>(x + (size_t)v * D)[threadIdx.x];
            float dx = e.x - xx.x, dy = e.y - xx.y, dz = e.z - xx.z, dw = e.w - xx.w;
            lsum = dx * dx + dy * dy + dz * dz + dw * dw;
            float4 qv;
            qv.x = xx.x + dx; qv.y = xx.y + dy; qv.z = xx.z + dz; qv.w = xx.w + dw;
            reinterpret_cast<float4*>(out + (size_t)v * D)[threadIdx.x] = qv;
        }
        if (threadIdx.x < 32) {
#pragma unroll
            for (int off = 8; off > 0; off >>= 1)
                lsum += __shfl_down_sync(0xffffffffu, lsum, off);
            if (threadIdx.x == 0) {
                if (out_size > QELEMS)
                    atomicAdd(out + QELEMS, lsum * (0.25f / (float)QELEMS));
                if (QELEMS + 1 + v < out_size) out[QELEMS + 1 + v] = (float)bfin;
            }
        }
    }
}

extern "C" void kernel_launch(void* const* d_in, const int* in_sizes, int n_in,
                              void* d_out, int out_size) {
    const float* x   = (const float*)d_in[0];
    const float* emb = (const float*)d_in[1];
    if (n_in >= 2 && in_sizes[0] == K * D && in_sizes[1] == QELEMS) {
        const float* t = x; x = emb; emb = t;
    }
    float* out = (float*)d_out;

    if (out_size > QELEMS)
        cudaMemsetAsync(out + QELEMS, 0, sizeof(float), 0);

    // reset per-tile completion counters every launch (graph-capturable memset)
    void* ctr_ptr = nullptr;
    cudaGetSymbolAddress(&ctr_ptr, g_tile_ctr);
    cudaMemsetAsync(ctr_ptr, 0, NTILES * sizeof(int), 0);

    cudaFuncSetAttribute(vq_gemm, cudaFuncAttributeMaxDynamicSharedMemorySize, SMEM_SZ);

    vq_convE<<<K * 8 / 256, 256>>>(emb);
    vq_gemm<<<CTAS, 256, SMEM_SZ>>>(x, emb, out, out_size);
    vq_rescan<<<256, 256>>>(x, emb, out, out_size);
}

// round 10
// speedup vs baseline: 1.4404x; 1.4404x over previous
#include <cuda_runtime.h>
#include <cuda_bf16.h>
#include <cstdint>

#define D        64
#define K        1024
#define NVEC     65536
#define QELEMS   (NVEC * D)
#define MTILE    128
#define NCHUNK   64
#define NCHUNKS  (K / NCHUNK)     // 16
#define GRID     (NVEC / MTILE)   // 512
#define BLOCK    128              // 4 warps; each warp M=32 rows
#define EPS      0.003f

// smem offsets
#define OFF_A    0            // 128 rows x 256B (swizzled) = 32768
#define OFF_B    32768        // 2 stages x 24576 (B1 16K + B2 8K)
#define OFF_SN   81920        // 1024 floats = 4096
#define OFF_IDX  86016        // 128 ints
#define OFF_FLG  86528        // 128 ints
#define OFF_RED  87040        // 4 floats
#define SMEM_SZ  87168

__device__ __nv_bfloat16 g_B1[K * 128];      // per codeword: [h | h]
__device__ __nv_bfloat16 g_B2[K * 64];       // per codeword: [m]
__device__ float g_enorm2[K];
__device__ int   g_flag_list[NVEC];
__device__ int   g_flag_count;

// ---------- helpers ----------
__device__ __forceinline__ uint32_t smem_u32(const void* p) {
    uint32_t a;
    asm("{ .reg .u64 t; cvta.to.shared.u64 t, %1; cvt.u32.u64 %0, t; }" : "=r"(a) : "l"(p));
    return a;
}
__device__ __forceinline__ void cp16(uint32_t dst, const void* src) {
    asm volatile("cp.async.cg.shared.global [%0], [%1], 16;" :: "r"(dst), "l"(src));
}
__device__ __forceinline__ void cp_commit() { asm volatile("cp.async.commit_group;" ::: "memory"); }
template<int N> __device__ __forceinline__ void cp_wait() {
    asm volatile("cp.async.wait_group %0;" :: "n"(N) : "memory");
}
__device__ __forceinline__ void ldsm4(uint32_t* r, uint32_t addr) {
    asm volatile("ldmatrix.sync.aligned.m8n8.x4.shared.b16 {%0,%1,%2,%3}, [%4];"
                 : "=r"(r[0]), "=r"(r[1]), "=r"(r[2]), "=r"(r[3]) : "r"(addr));
}
__device__ __forceinline__ void mma16816(float* c, const uint32_t* a, uint32_t b0, uint32_t b1) {
    asm volatile(
        "mma.sync.aligned.m16n8k16.row.col.f32.bf16.bf16.f32 "
        "{%0,%1,%2,%3}, {%4,%5,%6,%7}, {%8,%9}, {%0,%1,%2,%3};"
        : "+f"(c[0]), "+f"(c[1]), "+f"(c[2]), "+f"(c[3])
        : "r"(a[0]), "r"(a[1]), "r"(a[2]), "r"(a[3]), "r"(b0), "r"(b1));
}
__device__ __forceinline__ void sts16(uint32_t addr, uint4 v) {
    asm volatile("st.shared.v4.b32 [%0], {%1, %2, %3, %4};"
                 :: "r"(addr), "r"(v.x), "r"(v.y), "r"(v.z), "r"(v.w));
}

// ---------- codebook conversion ----------
__global__ void __launch_bounds__(256) vq_convE(const float* __restrict__ emb) {
    int t = blockIdx.x * 256 + threadIdx.x;
    if (t == 0) g_flag_count = 0;
    int k = t >> 3, j = t & 7;
    const float4* er = reinterpret_cast<const float4*>(emb + (size_t)k * D + j * 8);
    float4 a = er[0], b = er[1];
    float f[8] = {a.x, a.y, a.z, a.w, b.x, b.y, b.z, b.w};
    __nv_bfloat16 h[8], m[8];
    float s = 0.f;
#pragma unroll
    for (int e = 0; e < 8; e++) {
        s += f[e] * f[e];
        h[e] = __float2bfloat16_rn(f[e]);
        m[e] = __float2bfloat16_rn(f[e] - __bfloat162float(h[e]));
    }
    uint4 hv = *reinterpret_cast<uint4*>(h);
    uint4 mv = *reinterpret_cast<uint4*>(m);
    uint4* r1 = reinterpret_cast<uint4*>(g_B1 + (size_t)k * 128 + j * 8);
    r1[0] = hv; r1[8] = hv;
    *reinterpret_cast<uint4*>(g_B2 + (size_t)k * 64 + j * 8) = mv;
#pragma unroll
    for (int off = 4; off > 0; off >>= 1) s += __shfl_xor_sync(0xffffffffu, s, off);
    if (j == 0) g_enorm2[k] = s;
}

// load one B chunk with 128 threads: B1 (64x256B) + B2 (64x128B)
__device__ __forceinline__ void load_B(uint32_t sb, int chunk, int stage, int tid) {
    uint32_t base = sb + OFF_B + stage * 24576;
    const char* s1 = reinterpret_cast<const char*>(g_B1 + (size_t)chunk * NCHUNK * 128);
    const char* s2 = reinterpret_cast<const char*>(g_B2 + (size_t)chunk * NCHUNK * 64);
#pragma unroll
    for (int it = 0; it < 8; it++) {
        int i = tid + it * BLOCK;               // 0..1023
        int row = i >> 4, seg = i & 15;
        cp16(base + row * 256 + ((seg ^ (row & 7)) << 4), s1 + row * 256 + seg * 16);
    }
#pragma unroll
    for (int it = 0; it < 4; it++) {
        int i = tid + it * BLOCK;               // 0..511
        int row = i >> 3, seg = i & 7;
        cp16(base + 16384 + row * 128 + ((seg ^ (row & 7)) << 4), s2 + row * 128 + seg * 16);
    }
}

#define UPD(dv, nn, B1v, I1v, B2v) \
    if ((dv) < (B1v)) { (B2v) = (B1v); (B1v) = (dv); (I1v) = (nn); } \
    else if ((dv) < (B2v)) { (B2v) = (dv); }

#define MERGE(B1v, I1v, B2v, off) { \
    float p1 = __shfl_xor_sync(0xffffffffu, B1v, off); \
    int   pi = __shfl_xor_sync(0xffffffffu, I1v, off); \
    float p2 = __shfl_xor_sync(0xffffffffu, B2v, off); \
    if (p1 < (B1v) || (p1 == (B1v) && pi < (I1v))) { (B2v) = fminf((B1v), p2); (B1v) = p1; (I1v) = pi; } \
    else                                            { (B2v) = fminf((B2v), p1); } }

// ---------- mega kernel: A-convert + GEMM (2 A-blocks/warp) + argmin + finalize ----------
__global__ void __launch_bounds__(BLOCK, 2) vq_gemm(const float* __restrict__ x,
                                                    const float* __restrict__ emb,
                                                    float* __restrict__ out, int out_size) {
    extern __shared__ char sm[];
    uint32_t sb = smem_u32(sm);
    const int tid = threadIdx.x, wid = tid >> 5, l = tid & 31;

    // async loads: e-norms + B0 (G0), B1 (G1)
#pragma unroll
    for (int it = 0; it < 2; it++)
        cp16(sb + OFF_SN + (tid + it * BLOCK) * 16,
             reinterpret_cast<const char*>(g_enorm2) + (tid + it * BLOCK) * 16);
    load_B(sb, 0, 0, tid);
    cp_commit();                                // G0
    load_B(sb, 1, 1, tid);
    cp_commit();                                // G1

    // A tile: one row per thread, split h/m, STS swizzled
    {
        const int row = tid;
        const float4* xr = reinterpret_cast<const float4*>(
            x + (size_t)(blockIdx.x * MTILE + row) * D);
        uint32_t abase = sb + OFF_A + row * 256;
#pragma unroll
        for (int i = 0; i < 8; i++) {           // 8 x (8 floats -> 16B h + 16B m)
            float4 a = xr[2 * i], b = xr[2 * i + 1];
            float f[8] = {a.x, a.y, a.z, a.w, b.x, b.y, b.z, b.w};
            __nv_bfloat16 h[8], m[8];
#pragma unroll
            for (int e = 0; e < 8; e++) {
                h[e] = __float2bfloat16_rn(f[e]);
                m[e] = __float2bfloat16_rn(f[e] - __bfloat162float(h[e]));
            }
            sts16(abase + ((i ^ (row & 7)) << 4),       *reinterpret_cast<uint4*>(h));
            sts16(abase + (((8 + i) ^ (row & 7)) << 4), *reinterpret_cast<uint4*>(m));
        }
    }

    cp_wait<1>();
    __syncthreads();

    // hoist A fragments: 2 blocks of 16 rows per warp, 8 k-steps each
    uint32_t aF[2][8][4];
#pragma unroll
    for (int a = 0; a < 2; a++) {
        int row = (wid << 5) + (a << 4) + (l & 15);
        uint32_t rb = sb + OFF_A + row * 256;
#pragma unroll
        for (int j = 0; j < 8; j++) {
            int seg = j * 2 + (l >> 4);
            ldsm4(aF[a][j], rb + ((seg ^ (row & 7)) << 4));
        }
    }
    const float* snp = reinterpret_cast<const float*>(sm + OFF_SN);

    float b1a = 3.4e38f, b2a = 3.4e38f, b1b = 3.4e38f, b2b = 3.4e38f;
    float b1c = 3.4e38f, b2c = 3.4e38f, b1d = 3.4e38f, b2d = 3.4e38f;
    int i1a = 0, i1b = 0, i1c = 0, i1d = 0;

    for (int c = 0; c < NCHUNKS; c++) {
        if (c > 0) { cp_wait<1>(); __syncthreads(); }
        uint32_t stage = sb + OFF_B + (c & 1) * 24576;

        float C[2][8][4];
#pragma unroll
        for (int a = 0; a < 2; a++)
#pragma unroll
            for (int t = 0; t < 8; t++) { C[a][t][0]=C[a][t][1]=C[a][t][2]=C[a][t][3]=0.f; }

        // [h|m] x [h|h] (8 k-steps): 1 B-ldsm feeds 4 HMMA
#pragma unroll
        for (int j = 0; j < 8; j++) {
#pragma unroll
            for (int g = 0; g < 4; g++) {
                int row = (g << 4) + (l & 15);
                int seg = j * 2 + (l >> 4);
                uint32_t r[4];
                ldsm4(r, stage + row * 256 + ((seg ^ (row & 7)) << 4));
                mma16816(C[0][2*g],   aF[0][j], r[0], r[2]);
                mma16816(C[0][2*g+1], aF[0][j], r[1], r[3]);
                mma16816(C[1][2*g],   aF[1][j], r[0], r[2]);
                mma16816(C[1][2*g+1], aF[1][j], r[1], r[3]);
            }
        }
        // h x [m] (4 k-steps)
#pragma unroll
        for (int j = 0; j < 4; j++) {
#pragma unroll
            for (int g = 0; g < 4; g++) {
                int row = (g << 4) + (l & 15);
                int seg = j * 2 + (l >> 4);
                uint32_t r[4];
                ldsm4(r, stage + 16384 + row * 128 + ((seg ^ (row & 7)) << 4));
                mma16816(C[0][2*g],   aF[0][j], r[0], r[2]);
                mma16816(C[0][2*g+1], aF[0][j], r[1], r[3]);
                mma16816(C[1][2*g],   aF[1][j], r[0], r[2]);
                mma16816(C[1][2*g+1], aF[1][j], r[1], r[3]);
            }
        }

        // epilogue: two-min tracking for 4 row-slots
#pragma unroll
        for (int t = 0; t < 8; t++) {
            int n0 = c * NCHUNK + t * 8 + 2 * (l & 3);
            float s0 = snp[n0], s1 = snp[n0 + 1];
            float d;
            d = fmaf(-2.f, C[0][t][0], s0); UPD(d, n0,     b1a, i1a, b2a);
            d = fmaf(-2.f, C[0][t][1], s1); UPD(d, n0 + 1, b1a, i1a, b2a);
            d = fmaf(-2.f, C[0][t][2], s0); UPD(d, n0,     b1b, i1b, b2b);
            d = fmaf(-2.f, C[0][t][3], s1); UPD(d, n0 + 1, b1b, i1b, b2b);
            d = fmaf(-2.f, C[1][t][0], s0); UPD(d, n0,     b1c, i1c, b2c);
            d = fmaf(-2.f, C[1][t][1], s1); UPD(d, n0 + 1, b1c, i1c, b2c);
            d = fmaf(-2.f, C[1][t][2], s0); UPD(d, n0,     b1d, i1d, b2d);
            d = fmaf(-2.f, C[1][t][3], s1); UPD(d, n0 + 1, b1d, i1d, b2d);
        }

        __syncthreads();
        if (c + 2 < NCHUNKS) load_B(sb, c + 2, c & 1, tid);
        cp_commit();
    }

    // cross-lane merge within 4-lane groups
#pragma unroll
    for (int off = 1; off <= 2; off <<= 1) {
        MERGE(b1a, i1a, b2a, off);
        MERGE(b1b, i1b, b2b, off);
        MERGE(b1c, i1c, b2c, off);
        MERGE(b1d, i1d, b2d, off);
    }

    int* sidx = reinterpret_cast<int*>(sm + OFF_IDX);
    int* sflg = reinterpret_cast<int*>(sm + OFF_FLG);
    if ((l & 3) == 0) {
        int r0 = (wid << 5) + (l >> 2);         // rows r0, +8, +16, +24
        int v = blockIdx.x * MTILE + r0;
        int fa = (b2a - b1a <= EPS), fb = (b2b - b1b <= EPS);
        int fc = (b2c - b1c <= EPS), fd = (b2d - b1d <= EPS);
        sidx[r0]      = i1a; sflg[r0]      = fa;
        sidx[r0 + 8]  = i1b; sflg[r0 + 8]  = fb;
        sidx[r0 + 16] = i1c; sflg[r0 + 16] = fc;
        sidx[r0 + 24] = i1d; sflg[r0 + 24] = fd;
        if (fa) { int s = atomicAdd(&g_flag_count, 1); g_flag_list[s] = v; }
        if (fb) { int s = atomicAdd(&g_flag_count, 1); g_flag_list[s] = v + 8; }
        if (fc) { int s = atomicAdd(&g_flag_count, 1); g_flag_list[s] = v + 16; }
        if (fd) { int s = atomicAdd(&g_flag_count, 1); g_flag_list[s] = v + 24; }
    }
    __syncthreads();

    // fused finalize for non-flagged vectors (1 thread/vector)
    {
        const int r = tid;
        const int v = blockIdx.x * MTILE + r;
        float lsum = 0.f;
        if (!sflg[r]) {
            int bi = sidx[r];
            const float4* er = reinterpret_cast<const float4*>(emb + (size_t)bi * D);
            const float4* xr = reinterpret_cast<const float4*>(x + (size_t)v * D);
            float4* o = reinterpret_cast<float4*>(out + (size_t)v * D);
#pragma unroll
            for (int i = 0; i < 16; i++) {
                float4 e = er[i]; float4 xx = xr[i];
                float dx = e.x - xx.x, dy = e.y - xx.y, dz = e.z - xx.z, dw = e.w - xx.w;
                lsum += dx * dx + dy * dy + dz * dz + dw * dw;
                float4 q;   // quantized = x + (e - x)
                q.x = xx.x + dx; q.y = xx.y + dy; q.z = xx.z + dz; q.w = xx.w + dw;
                o[i] = q;
            }
            if (QELEMS + 1 + v < out_size) out[QELEMS + 1 + v] = (float)bi;
        }
#pragma unroll
        for (int off = 16; off > 0; off >>= 1)
            lsum += __shfl_down_sync(0xffffffffu, lsum, off);
        float* sred = reinterpret_cast<float*>(sm + OFF_RED);
        if (l == 0) sred[wid] = lsum;
        __syncthreads();
        if (wid == 0) {
            float s = (l < 4) ? sred[l] : 0.f;
#pragma unroll
            for (int off = 2; off > 0; off >>= 1)
                s += __shfl_down_sync(0xffffffffu, s, off);
            if (l == 0 && out_size > QELEMS)
                atomicAdd(out + QELEMS, s * (0.25f / (float)QELEMS));
        }
    }
}

// ---------- exact rescan + full finalize for flagged vectors ----------
__global__ void __launch_bounds__(256) vq_rescan(const float* __restrict__ x,
                                                 const float* __restrict__ emb,
                                                 float* __restrict__ out, int out_size) {
    __shared__ float sx[64];
    __shared__ float sbest[256];
    __shared__ int   sidx[256];
    int n = g_flag_count;
    if (n > NVEC) n = NVEC;
    for (int vi = blockIdx.x; vi < n; vi += gridDim.x) {
        int v = g_flag_list[vi];
        __syncthreads();
        if (threadIdx.x < 16)
            reinterpret_cast<float4*>(sx)[threadIdx.x] =
                reinterpret_cast<const float4*>(x + (size_t)v * D)[threadIdx.x];
        __syncthreads();
        float best = 3.4e38f; int bi = K;
#pragma unroll
        for (int kk = 0; kk < 4; kk++) {
            int k = kk * 256 + threadIdx.x;
            const float4* er = reinterpret_cast<const float4*>(emb + (size_t)k * D);
            float dot = 0.f;
#pragma unroll
            for (int i = 0; i < 16; i++) {
                float4 e = er[i];
                dot += sx[4*i] * e.x + sx[4*i+1] * e.y + sx[4*i+2] * e.z + sx[4*i+3] * e.w;
            }
            float d = fmaf(-2.f, dot, g_enorm2[k]);
            if (d < best) { best = d; bi = k; }
        }
        sbest[threadIdx.x] = best; sidx[threadIdx.x] = bi;
        __syncthreads();
        for (int s = 128; s > 0; s >>= 1) {
            if (threadIdx.x < s) {
                float ob = sbest[threadIdx.x + s]; int oi = sidx[threadIdx.x + s];
                if (ob < sbest[threadIdx.x] ||
                    (ob == sbest[threadIdx.x] && oi < sidx[threadIdx.x])) {
                    sbest[threadIdx.x] = ob; sidx[threadIdx.x] = oi;
                }
            }
            __syncthreads();
        }
        int bfin = sidx[0];
        float lsum = 0.f;
        if (threadIdx.x < 16) {
            float4 e  = reinterpret_cast<const float4*>(emb + (size_t)bfin * D)[threadIdx.x];
            float4 xx = reinterpret_cast<const float4*>(x + (size_t)v * D)[threadIdx.x];
            float dx = e.x - xx.x, dy = e.y - xx.y, dz = e.z - xx.z, dw = e.w - xx.w;
            lsum = dx * dx + dy * dy + dz * dz + dw * dw;
            float4 q;
            q.x = xx.x + dx; q.y = xx.y + dy; q.z = xx.z + dz; q.w = xx.w + dw;
            reinterpret_cast<float4*>(out + (size_t)v * D)[threadIdx.x] = q;
        }
        if (threadIdx.x < 32) {
#pragma unroll
            for (int off = 8; off > 0; off >>= 1)
                lsum += __shfl_down_sync(0xffffffffu, lsum, off);
            if (threadIdx.x == 0) {
                if (out_size > QELEMS)
                    atomicAdd(out + QELEMS, lsum * (0.25f / (float)QELEMS));
                if (QELEMS + 1 + v < out_size) out[QELEMS + 1 + v] = (float)bfin;
            }
        }
    }
}

extern "C" void kernel_launch(void* const* d_in, const int* in_sizes, int n_in,
                              void* d_out, int out_size) {
    const float* x   = (const float*)d_in[0];
    const float* emb = (const float*)d_in[1];
    if (n_in >= 2 && in_sizes[0] == K * D && in_sizes[1] == QELEMS) {
        const float* t = x; x = emb; emb = t;
    }
    float* out = (float*)d_out;

    if (out_size > QELEMS)
        cudaMemsetAsync(out + QELEMS, 0, sizeof(float), 0);

    cudaFuncSetAttribute(vq_gemm, cudaFuncAttributeMaxDynamicSharedMemorySize, SMEM_SZ);

    vq_convE<<<K * 8 / 256, 256>>>(emb);
    vq_gemm<<<GRID, BLOCK, SMEM_SZ>>>(x, emb, out, out_size);
    vq_rescan<<<256, 256>>>(x, emb, out, out_size);
}